// round 1
// baseline (speedup 1.0000x reference)
#include <cuda_runtime.h>
#include <cstdint>

// Problem-scale constants (sizes verified at launch from in_sizes).
#define NMAX (1 << 20)

// Scratch (static device globals — no runtime allocation allowed).
// g_T: per-node local affine transform, 3 rows of [r0 r1 r2 | t] as float4 (48B/node, 48MB).
__device__ float4 g_T[3 * NMAX];
// g_coords: global coordinates per node (16MB).
__device__ float4 g_coords[NMAX];
// Energy accumulator (double for summation robustness).
__device__ double g_acc;

// ---------------------------------------------------------------------------
__global__ void k_zero_acc() { g_acc = 0.0; }

// Build local transform from a DOF row (phi, theta, d = first 3 of 9).
__device__ __forceinline__ void write_local_T(int node, float phi, float theta, float d) {
    float sp, cp, st, ct;
    sincosf(phi, &sp, &cp);
    sincosf(theta, &st, &ct);
    float r00 = cp * ct, r01 = -sp, r02 = cp * st;
    float r10 = sp * ct, r11 = cp, r12 = sp * st;
    float r20 = -st, r21 = 0.0f, r22 = ct;
    g_T[3 * node + 0] = make_float4(r00, r01, r02, d * r00);
    g_T[3 * node + 1] = make_float4(r10, r11, r12, d * r10);
    g_T[3 * node + 2] = make_float4(r20, r21, r22, d * r20);
}

__global__ void k_local_base(const float* __restrict__ dofs, int n) {
    int i = blockIdx.x * blockDim.x + threadIdx.x;
    if (i >= n) return;
    const float* row = dofs + (size_t)i * 9;
    write_local_T(i, row[0], row[1], row[2]);
}

__global__ void k_local_masked(const float* __restrict__ mdofs,
                               const int* __restrict__ mask_idx, int k) {
    int j = blockIdx.x * blockDim.x + threadIdx.x;
    if (j >= k) return;
    int i = mask_idx[j];
    const float* row = mdofs + (size_t)j * 9;
    write_local_T(i, row[0], row[1], row[2]);
}

// ---------------------------------------------------------------------------
// Chain walk: coords[i] = translation of L[a_k]...L[a_1]L[i] applied to origin,
// where a_1 = parent(i), ... terminating at node 0 (whose transform is identity,
// matching T.at[0].set(eye) in the reference — we simply never apply node 0).
__global__ void k_coords(const int* __restrict__ parent, int n) {
    int i = blockIdx.x * blockDim.x + threadIdx.x;
    if (i >= n) return;
    if (i == 0) {
        g_coords[0] = make_float4(0.f, 0.f, 0.f, 0.f);
        return;
    }
    float4 r0 = g_T[3 * i + 0];
    float4 r1 = g_T[3 * i + 1];
    float4 r2 = g_T[3 * i + 2];
    float vx = r0.w, vy = r1.w, vz = r2.w;
    int a = parent[i];
    while (a != 0) {
        float4 q0 = g_T[3 * a + 0];
        float4 q1 = g_T[3 * a + 1];
        float4 q2 = g_T[3 * a + 2];
        int an = parent[a];  // issue next-parent load early (independent)
        float nx = fmaf(q0.x, vx, fmaf(q0.y, vy, fmaf(q0.z, vz, q0.w)));
        float ny = fmaf(q1.x, vx, fmaf(q1.y, vy, fmaf(q1.z, vz, q1.w)));
        float nz = fmaf(q2.x, vx, fmaf(q2.y, vy, fmaf(q2.z, vz, q2.w)));
        vx = nx; vy = ny; vz = nz;
        a = an;
    }
    g_coords[i] = make_float4(vx, vy, vz, 0.f);
}

// ---------------------------------------------------------------------------
__device__ __forceinline__ float3 f3sub(float4 a, float4 b) {
    return make_float3(a.x - b.x, a.y - b.y, a.z - b.z);
}
__device__ __forceinline__ float3 f3cross(float3 a, float3 b) {
    return make_float3(a.y * b.z - a.z * b.y,
                       a.z * b.x - a.x * b.z,
                       a.x * b.y - a.y * b.x);
}
__device__ __forceinline__ float f3dot(float3 a, float3 b) {
    return fmaf(a.x, b.x, fmaf(a.y, b.y, a.z * b.z));
}

__global__ void k_energy(const int* __restrict__ torsion_atoms,
                         const float* __restrict__ k_tor,
                         const float* __restrict__ n_per,
                         const float* __restrict__ delta,
                         int m) {
    int t = blockIdx.x * blockDim.x + threadIdx.x;
    float e = 0.0f;
    if (t < m) {
        int4 ta = reinterpret_cast<const int4*>(torsion_atoms)[t];
        float4 p1 = g_coords[ta.x];
        float4 p2 = g_coords[ta.y];
        float4 p3 = g_coords[ta.z];
        float4 p4 = g_coords[ta.w];
        float3 b1 = f3sub(p2, p1);
        float3 b2 = f3sub(p3, p2);
        float3 b3 = f3sub(p4, p3);
        float3 n1 = f3cross(b1, b2);
        float3 n2 = f3cross(b2, b3);
        float inv = 1.0f / (sqrtf(f3dot(b2, b2)) + 1e-8f);
        float3 b2n = make_float3(b2.x * inv, b2.y * inv, b2.z * inv);
        float y = f3dot(f3cross(n1, n2), b2n);
        float x = f3dot(n1, n2);
        float chi = atan2f(y, x);
        e = k_tor[t] * (1.0f + cosf(fmaf(n_per[t], chi, -delta[t])));
    }
    // Block reduction: warp shuffles, then cross-warp via shared, then one
    // double atomicAdd per block.
    #pragma unroll
    for (int o = 16; o > 0; o >>= 1)
        e += __shfl_down_sync(0xffffffffu, e, o);
    __shared__ float s_warp[8];
    int lane = threadIdx.x & 31;
    int wrp = threadIdx.x >> 5;
    if (lane == 0) s_warp[wrp] = e;
    __syncthreads();
    if (wrp == 0) {
        float v = (lane < (blockDim.x >> 5)) ? s_warp[lane] : 0.0f;
        #pragma unroll
        for (int o = 4; o > 0; o >>= 1)
            v += __shfl_down_sync(0xffffffffu, v, o);
        if (lane == 0) atomicAdd(&g_acc, (double)v);
    }
}

__global__ void k_finalize(float* __restrict__ out) {
    out[0] = (float)g_acc;
}

// ---------------------------------------------------------------------------
extern "C" void kernel_launch(void* const* d_in, const int* in_sizes, int n_in,
                              void* d_out, int out_size) {
    const float* masked_dofs = (const float*)d_in[0];   // (K, 9)
    const float* full_dofs   = (const float*)d_in[1];   // (N, 9)
    const float* k_tor       = (const float*)d_in[2];   // (M,)
    const float* n_per       = (const float*)d_in[3];   // (M,)
    const float* delta       = (const float*)d_in[4];   // (M,)
    const int*   mask_idx    = (const int*)d_in[5];     // (K,)
    const int*   parent      = (const int*)d_in[6];     // (N,)
    const int*   tors        = (const int*)d_in[7];     // (M, 4)

    int K = in_sizes[0] / 9;
    int N = in_sizes[1] / 9;
    int M = in_sizes[2];

    const int TB = 256;
    k_zero_acc<<<1, 1>>>();
    k_local_base<<<(N + TB - 1) / TB, TB>>>(full_dofs, N);
    k_local_masked<<<(K + TB - 1) / TB, TB>>>(masked_dofs, mask_idx, K);
    k_coords<<<(N + TB - 1) / TB, TB>>>(parent, N);
    k_energy<<<(M + TB - 1) / TB, TB>>>(tors, k_tor, n_per, delta, M);
    k_finalize<<<1, 1>>>((float*)d_out);
}

// round 4
// speedup vs baseline: 1.6127x; 1.6127x over previous
#include <cuda_runtime.h>
#include <cstdint>

#define NMAX (1 << 20)
#define SCACHE (1 << 16)   // nodes with precomputed full global transforms

// Scratch (static device globals — no runtime allocation allowed).
__device__ float4 g_T[3 * NMAX];      // local transforms, 3 rows [r|t] per node (48MB)
__device__ float4 g_G[3 * SCACHE];    // global transforms for first SCACHE nodes (3MB)
__device__ float4 g_coords[NMAX];     // global coordinates (16MB)
__device__ double g_acc;

// ---------------------------------------------------------------------------
__global__ void k_zero_acc() { g_acc = 0.0; }

__device__ __forceinline__ void write_local_T(int node, float phi, float theta, float d) {
    float sp, cp, st, ct;
    sincosf(phi, &sp, &cp);
    sincosf(theta, &st, &ct);
    float r00 = cp * ct, r02 = cp * st;
    float r10 = sp * ct, r12 = sp * st;
    g_T[3 * node + 0] = make_float4(r00, -sp, r02, d * r00);
    g_T[3 * node + 1] = make_float4(r10,  cp, r12, d * r10);
    g_T[3 * node + 2] = make_float4(-st, 0.f, ct,  d * -st);
}

__global__ void k_local_base(const float* __restrict__ dofs, int n) {
    int i = blockIdx.x * blockDim.x + threadIdx.x;
    if (i >= n) return;
    const float* row = dofs + (size_t)i * 9;
    write_local_T(i, row[0], row[1], row[2]);
}

__global__ void k_local_masked(const float* __restrict__ mdofs,
                               const int* __restrict__ mask_idx, int k) {
    int j = blockIdx.x * blockDim.x + threadIdx.x;
    if (j >= k) return;
    int i = mask_idx[j];
    const float* row = mdofs + (size_t)j * 9;
    write_local_T(i, row[0], row[1], row[2]);
}

// ---------------------------------------------------------------------------
// Build full global transforms for nodes < SCACHE by walking to the root with
// full 3x4 composition. Chain indices strictly decrease, so the whole walk
// touches only g_T[< SCACHE] (~3MB, L2 resident). Node 0's transform is
// identity per the reference (T.at[0].set(eye)), so we never apply it.
__global__ void k_glob(const int* __restrict__ parent, int s) {
    int i = blockIdx.x * blockDim.x + threadIdx.x;
    if (i >= s) return;
    if (i == 0) {
        g_G[0] = make_float4(1.f, 0.f, 0.f, 0.f);
        g_G[1] = make_float4(0.f, 1.f, 0.f, 0.f);
        g_G[2] = make_float4(0.f, 0.f, 1.f, 0.f);
        return;
    }
    float4 a0 = g_T[3 * i + 0];
    float4 a1 = g_T[3 * i + 1];
    float4 a2 = g_T[3 * i + 2];
    int a = parent[i];
    while (a != 0) {
        float4 q0 = g_T[3 * a + 0];
        float4 q1 = g_T[3 * a + 1];
        float4 q2 = g_T[3 * a + 2];
        int an = parent[a];
        float4 n0, n1, n2;
        n0.x = fmaf(q0.x, a0.x, fmaf(q0.y, a1.x, q0.z * a2.x));
        n0.y = fmaf(q0.x, a0.y, fmaf(q0.y, a1.y, q0.z * a2.y));
        n0.z = fmaf(q0.x, a0.z, fmaf(q0.y, a1.z, q0.z * a2.z));
        n0.w = fmaf(q0.x, a0.w, fmaf(q0.y, a1.w, fmaf(q0.z, a2.w, q0.w)));
        n1.x = fmaf(q1.x, a0.x, fmaf(q1.y, a1.x, q1.z * a2.x));
        n1.y = fmaf(q1.x, a0.y, fmaf(q1.y, a1.y, q1.z * a2.y));
        n1.z = fmaf(q1.x, a0.z, fmaf(q1.y, a1.z, q1.z * a2.z));
        n1.w = fmaf(q1.x, a0.w, fmaf(q1.y, a1.w, fmaf(q1.z, a2.w, q1.w)));
        n2.x = fmaf(q2.x, a0.x, fmaf(q2.y, a1.x, q2.z * a2.x));
        n2.y = fmaf(q2.x, a0.y, fmaf(q2.y, a1.y, q2.z * a2.y));
        n2.z = fmaf(q2.x, a0.z, fmaf(q2.y, a1.z, q2.z * a2.z));
        n2.w = fmaf(q2.x, a0.w, fmaf(q2.y, a1.w, fmaf(q2.z, a2.w, q2.w)));
        a0 = n0; a1 = n1; a2 = n2;
        a = an;
    }
    g_G[3 * i + 0] = a0;
    g_G[3 * i + 1] = a1;
    g_G[3 * i + 2] = a2;
}

// ---------------------------------------------------------------------------
// Main walk: accumulate translation upward until the chain drops below SCACHE,
// then apply that node's cached global transform once.
__global__ void k_coords(const int* __restrict__ parent, int n) {
    int i = blockIdx.x * blockDim.x + threadIdx.x;
    if (i >= n) return;
    if (i < SCACHE) {
        g_coords[i] = make_float4(g_G[3 * i + 0].w, g_G[3 * i + 1].w,
                                  g_G[3 * i + 2].w, 0.f);
        return;
    }
    float4 r0 = g_T[3 * i + 0];
    float4 r1 = g_T[3 * i + 1];
    float4 r2 = g_T[3 * i + 2];
    float vx = r0.w, vy = r1.w, vz = r2.w;
    int a = parent[i];
    while (a >= SCACHE) {
        float4 q0 = g_T[3 * a + 0];
        float4 q1 = g_T[3 * a + 1];
        float4 q2 = g_T[3 * a + 2];
        int an = parent[a];
        float nx = fmaf(q0.x, vx, fmaf(q0.y, vy, fmaf(q0.z, vz, q0.w)));
        float ny = fmaf(q1.x, vx, fmaf(q1.y, vy, fmaf(q1.z, vz, q1.w)));
        float nz = fmaf(q2.x, vx, fmaf(q2.y, vy, fmaf(q2.z, vz, q2.w)));
        vx = nx; vy = ny; vz = nz;
        a = an;
    }
    float4 G0 = g_G[3 * a + 0];
    float4 G1 = g_G[3 * a + 1];
    float4 G2 = g_G[3 * a + 2];
    float cx = fmaf(G0.x, vx, fmaf(G0.y, vy, fmaf(G0.z, vz, G0.w)));
    float cy = fmaf(G1.x, vx, fmaf(G1.y, vy, fmaf(G1.z, vz, G1.w)));
    float cz = fmaf(G2.x, vx, fmaf(G2.y, vy, fmaf(G2.z, vz, G2.w)));
    g_coords[i] = make_float4(cx, cy, cz, 0.f);
}

// ---------------------------------------------------------------------------
__device__ __forceinline__ float3 f3sub(float4 a, float4 b) {
    return make_float3(a.x - b.x, a.y - b.y, a.z - b.z);
}
__device__ __forceinline__ float3 f3cross(float3 a, float3 b) {
    return make_float3(a.y * b.z - a.z * b.y,
                       a.z * b.x - a.x * b.z,
                       a.x * b.y - a.y * b.x);
}
__device__ __forceinline__ float f3dot(float3 a, float3 b) {
    return fmaf(a.x, b.x, fmaf(a.y, b.y, a.z * b.z));
}

__global__ void k_energy(const int* __restrict__ torsion_atoms,
                         const float* __restrict__ k_tor,
                         const float* __restrict__ n_per,
                         const float* __restrict__ delta,
                         int m) {
    int t = blockIdx.x * blockDim.x + threadIdx.x;
    float e = 0.0f;
    if (t < m) {
        int4 ta = reinterpret_cast<const int4*>(torsion_atoms)[t];
        float4 p1 = g_coords[ta.x];
        float4 p2 = g_coords[ta.y];
        float4 p3 = g_coords[ta.z];
        float4 p4 = g_coords[ta.w];
        float3 b1 = f3sub(p2, p1);
        float3 b2 = f3sub(p3, p2);
        float3 b3 = f3sub(p4, p3);
        float3 n1 = f3cross(b1, b2);
        float3 n2 = f3cross(b2, b3);
        float inv = 1.0f / (sqrtf(f3dot(b2, b2)) + 1e-8f);
        float3 b2n = make_float3(b2.x * inv, b2.y * inv, b2.z * inv);
        float y = f3dot(f3cross(n1, n2), b2n);
        float x = f3dot(n1, n2);
        float chi = atan2f(y, x);
        e = k_tor[t] * (1.0f + cosf(fmaf(n_per[t], chi, -delta[t])));
    }
    #pragma unroll
    for (int o = 16; o > 0; o >>= 1)
        e += __shfl_down_sync(0xffffffffu, e, o);
    __shared__ float s_warp[8];
    int lane = threadIdx.x & 31;
    int wrp = threadIdx.x >> 5;
    if (lane == 0) s_warp[wrp] = e;
    __syncthreads();
    if (wrp == 0) {
        float v = (lane < (blockDim.x >> 5)) ? s_warp[lane] : 0.0f;
        #pragma unroll
        for (int o = 4; o > 0; o >>= 1)
            v += __shfl_down_sync(0xffffffffu, v, o);
        if (lane == 0) atomicAdd(&g_acc, (double)v);
    }
}

__global__ void k_finalize(float* __restrict__ out) {
    out[0] = (float)g_acc;
}

// ---------------------------------------------------------------------------
extern "C" void kernel_launch(void* const* d_in, const int* in_sizes, int n_in,
                              void* d_out, int out_size) {
    const float* masked_dofs = (const float*)d_in[0];
    const float* full_dofs   = (const float*)d_in[1];
    const float* k_tor       = (const float*)d_in[2];
    const float* n_per       = (const float*)d_in[3];
    const float* delta       = (const float*)d_in[4];
    const int*   mask_idx    = (const int*)d_in[5];
    const int*   parent      = (const int*)d_in[6];
    const int*   tors        = (const int*)d_in[7];

    int K = in_sizes[0] / 9;
    int N = in_sizes[1] / 9;
    int M = in_sizes[2];
    int S = (N < SCACHE) ? N : SCACHE;

    const int TB = 256;
    k_zero_acc<<<1, 1>>>();
    k_local_base<<<(N + TB - 1) / TB, TB>>>(full_dofs, N);
    k_local_masked<<<(K + TB - 1) / TB, TB>>>(masked_dofs, mask_idx, K);
    k_glob<<<(S + TB - 1) / TB, TB>>>(parent, S);
    k_coords<<<(N + TB - 1) / TB, TB>>>(parent, N);
    k_energy<<<(M + TB - 1) / TB, TB>>>(tors, k_tor, n_per, delta, M);
    k_finalize<<<1, 1>>>((float*)d_out);
}

// round 5
// speedup vs baseline: 1.8670x; 1.1576x over previous
#include <cuda_runtime.h>
#include <cstdint>

#define NMAX (1 << 20)
#define L1B  4096      // ladder level 1 boundary
#define L2B  65536     // ladder level 2 boundary
#define L3B  262144    // ladder level 3 boundary (top cache)

// Scratch (static device globals; zero-initialized at load).
__device__ float4 g_cs[NMAX];      // (cos phi, sin phi, cos theta, sin theta)  16MB
__device__ float  g_d[NMAX];       // bond length d                              4MB
__device__ float4 g_G[3 * L3B];    // full global transforms for nodes < L3B    12MB
__device__ float4 g_coords[NMAX];  // global coordinates                        16MB
__device__ double g_acc;
__device__ unsigned g_done;
__device__ int g_notIota;

// Apply rotation R(phi,theta) from compact form: 8 flops.
// q = (cp, sp, ct, st). out = R * v.
#define ROT(q, ivx, ivy, ivz, ox, oy, oz)            \
    {                                                \
        float _u = fmaf((q).z, (ivx), (q).w * (ivz)); \
        (oz) = fmaf((q).z, (ivz), -(q).w * (ivx));    \
        (ox) = fmaf((q).x, _u, -(q).y * (ivy));       \
        (oy) = fmaf((q).y, _u, (q).x * (ivy));        \
    }

// ---------------------------------------------------------------------------
// Verify mask_idx == arange(K). Sets g_notIota if not (reset by k_energy).
__global__ void k_check(const int* __restrict__ mask_idx, int k) {
    for (int j = blockIdx.x * blockDim.x + threadIdx.x; j < k;
         j += gridDim.x * blockDim.x)
        if (mask_idx[j] != j) g_notIota = 1;
}

// Build compact transform params for every node. If mask is the identity
// iota (common case), masked rows are folded in directly.
__global__ void k_local(const float* __restrict__ full,
                        const float* __restrict__ masked, int n, int k) {
    int i = blockIdx.x * blockDim.x + threadIdx.x;
    if (i >= n) return;
    const float* row = (g_notIota == 0 && i < k) ? (masked + (size_t)i * 9)
                                                 : (full + (size_t)i * 9);
    float phi = row[0], theta = row[1], d = row[2];
    float sp, cp, st, ct;
    sincosf(phi, &sp, &cp);
    sincosf(theta, &st, &ct);
    g_cs[i] = make_float4(cp, sp, ct, st);
    g_d[i] = d;
}

// Fallback scatter (only does work if mask_idx was not iota).
__global__ void k_scatter(const float* __restrict__ masked,
                          const int* __restrict__ mask_idx, int k) {
    if (g_notIota == 0) return;
    for (int j = blockIdx.x * blockDim.x + threadIdx.x; j < k;
         j += gridDim.x * blockDim.x) {
        int i = mask_idx[j];
        const float* row = masked + (size_t)j * 9;
        float phi = row[0], theta = row[1], d = row[2];
        float sp, cp, st, ct;
        sincosf(phi, &sp, &cp);
        sincosf(theta, &st, &ct);
        g_cs[i] = make_float4(cp, sp, ct, st);
        g_d[i] = d;
    }
}

// ---------------------------------------------------------------------------
// Ladder level: for i in [start, end), compose the full 3x4 global transform
// by walking parents until index < stop, then composing with the cached
// global transform. Node 0 is identity (reference sets T[0]=eye).
__global__ void k_glob(const int* __restrict__ parent, int start, int end,
                       int stop) {
    int i = start + blockIdx.x * blockDim.x + threadIdx.x;
    if (i >= end) return;
    if (i == 0) {
        g_G[0] = make_float4(1.f, 0.f, 0.f, 0.f);
        g_G[1] = make_float4(0.f, 1.f, 0.f, 0.f);
        g_G[2] = make_float4(0.f, 0.f, 1.f, 0.f);
        g_coords[0] = make_float4(0.f, 0.f, 0.f, 0.f);
        return;
    }
    float4 cs = g_cs[i];
    float d = g_d[i];
    // A = L(i)
    float4 r0 = make_float4(cs.x * cs.z, -cs.y, cs.x * cs.w, d * cs.x * cs.z);
    float4 r1 = make_float4(cs.y * cs.z, cs.x, cs.y * cs.w, d * cs.y * cs.z);
    float4 r2 = make_float4(-cs.w, 0.f, cs.z, -d * cs.w);
    int a = parent[i];
    while (a >= stop) {
        float4 q = g_cs[a];
        float qd = g_d[a];
        int an = parent[a];
        float n0x, n1x, n2x, n0y, n1y, n2y, n0z, n1z, n2z, n0w, n1w, n2w;
        ROT(q, r0.x, r1.x, r2.x, n0x, n1x, n2x);
        ROT(q, r0.y, r1.y, r2.y, n0y, n1y, n2y);
        ROT(q, r0.z, r1.z, r2.z, n0z, n1z, n2z);
        float w = r0.w + qd;
        ROT(q, w, r1.w, r2.w, n0w, n1w, n2w);
        r0 = make_float4(n0x, n0y, n0z, n0w);
        r1 = make_float4(n1x, n1y, n1z, n1w);
        r2 = make_float4(n2x, n2y, n2z, n2w);
        a = an;
    }
    if (a > 0) {  // compose with cached global (a==0 -> identity, skip)
        float4 G0 = g_G[3 * a + 0];
        float4 G1 = g_G[3 * a + 1];
        float4 G2 = g_G[3 * a + 2];
        float4 n0, n1, n2;
        n0.x = fmaf(G0.x, r0.x, fmaf(G0.y, r1.x, G0.z * r2.x));
        n0.y = fmaf(G0.x, r0.y, fmaf(G0.y, r1.y, G0.z * r2.y));
        n0.z = fmaf(G0.x, r0.z, fmaf(G0.y, r1.z, G0.z * r2.z));
        n0.w = fmaf(G0.x, r0.w, fmaf(G0.y, r1.w, fmaf(G0.z, r2.w, G0.w)));
        n1.x = fmaf(G1.x, r0.x, fmaf(G1.y, r1.x, G1.z * r2.x));
        n1.y = fmaf(G1.x, r0.y, fmaf(G1.y, r1.y, G1.z * r2.y));
        n1.z = fmaf(G1.x, r0.z, fmaf(G1.y, r1.z, G1.z * r2.z));
        n1.w = fmaf(G1.x, r0.w, fmaf(G1.y, r1.w, fmaf(G1.z, r2.w, G1.w)));
        n2.x = fmaf(G2.x, r0.x, fmaf(G2.y, r1.x, G2.z * r2.x));
        n2.y = fmaf(G2.x, r0.y, fmaf(G2.y, r1.y, G2.z * r2.y));
        n2.z = fmaf(G2.x, r0.z, fmaf(G2.y, r1.z, G2.z * r2.z));
        n2.w = fmaf(G2.x, r0.w, fmaf(G2.y, r1.w, fmaf(G2.z, r2.w, G2.w)));
        r0 = n0; r1 = n1; r2 = n2;
    }
    g_G[3 * i + 0] = r0;
    g_G[3 * i + 1] = r1;
    g_G[3 * i + 2] = r2;
    g_coords[i] = make_float4(r0.w, r1.w, r2.w, 0.f);
}

// ---------------------------------------------------------------------------
// Main walk for i >= L3B: translation-only hops until below L3B, then one
// affine apply of the cached global transform.
__global__ void k_coords(const int* __restrict__ parent, int n) {
    int i = L3B + blockIdx.x * blockDim.x + threadIdx.x;
    if (i >= n) return;
    float4 cs = g_cs[i];
    float d = g_d[i];
    float vx, vy, vz;
    ROT(cs, d, 0.f, 0.f, vx, vy, vz);  // t_i = R_i * (d,0,0)
    int a = parent[i];
    while (a >= L3B) {
        float4 q = g_cs[a];
        float qd = g_d[a];
        int an = parent[a];
        float w = vx + qd, nx, ny, nz;
        ROT(q, w, vy, vz, nx, ny, nz);
        vx = nx; vy = ny; vz = nz;
        a = an;
    }
    if (a > 0) {
        float4 G0 = g_G[3 * a + 0];
        float4 G1 = g_G[3 * a + 1];
        float4 G2 = g_G[3 * a + 2];
        float cx = fmaf(G0.x, vx, fmaf(G0.y, vy, fmaf(G0.z, vz, G0.w)));
        float cy = fmaf(G1.x, vx, fmaf(G1.y, vy, fmaf(G1.z, vz, G1.w)));
        float cz = fmaf(G2.x, vx, fmaf(G2.y, vy, fmaf(G2.z, vz, G2.w)));
        vx = cx; vy = cy; vz = cz;
    }
    g_coords[i] = make_float4(vx, vy, vz, 0.f);
}

// ---------------------------------------------------------------------------
__device__ __forceinline__ float3 f3sub(float4 a, float4 b) {
    return make_float3(a.x - b.x, a.y - b.y, a.z - b.z);
}
__device__ __forceinline__ float3 f3cross(float3 a, float3 b) {
    return make_float3(a.y * b.z - a.z * b.y,
                       a.z * b.x - a.x * b.z,
                       a.x * b.y - a.y * b.x);
}
__device__ __forceinline__ float f3dot(float3 a, float3 b) {
    return fmaf(a.x, b.x, fmaf(a.y, b.y, a.z * b.z));
}

__global__ void k_energy(const int* __restrict__ torsion_atoms,
                         const float* __restrict__ k_tor,
                         const float* __restrict__ n_per,
                         const float* __restrict__ delta,
                         int m, float* __restrict__ out) {
    int t = blockIdx.x * blockDim.x + threadIdx.x;
    float e = 0.0f;
    if (t < m) {
        int4 ta = reinterpret_cast<const int4*>(torsion_atoms)[t];
        float4 p1 = g_coords[ta.x];
        float4 p2 = g_coords[ta.y];
        float4 p3 = g_coords[ta.z];
        float4 p4 = g_coords[ta.w];
        float3 b1 = f3sub(p2, p1);
        float3 b2 = f3sub(p3, p2);
        float3 b3 = f3sub(p4, p3);
        float3 n1 = f3cross(b1, b2);
        float3 n2 = f3cross(b2, b3);
        float inv = 1.0f / (sqrtf(f3dot(b2, b2)) + 1e-8f);
        float3 b2n = make_float3(b2.x * inv, b2.y * inv, b2.z * inv);
        float y = f3dot(f3cross(n1, n2), b2n);
        float x = f3dot(n1, n2);
        float chi = atan2f(y, x);
        e = k_tor[t] * (1.0f + cosf(fmaf(n_per[t], chi, -delta[t])));
    }
    #pragma unroll
    for (int o = 16; o > 0; o >>= 1)
        e += __shfl_down_sync(0xffffffffu, e, o);
    __shared__ float s_warp[8];
    int lane = threadIdx.x & 31;
    int wrp = threadIdx.x >> 5;
    if (lane == 0) s_warp[wrp] = e;
    __syncthreads();
    if (wrp == 0) {
        float v = (lane < (blockDim.x >> 5)) ? s_warp[lane] : 0.0f;
        #pragma unroll
        for (int o = 4; o > 0; o >>= 1)
            v += __shfl_down_sync(0xffffffffu, v, o);
        if (lane == 0) {
            atomicAdd(&g_acc, (double)v);
            __threadfence();
            unsigned done = atomicInc(&g_done, 0xffffffffu);
            if (done == gridDim.x - 1) {
                // Last block: publish result and reset state for next replay.
                double total = atomicAdd(&g_acc, 0.0);
                out[0] = (float)total;
                g_acc = 0.0;
                g_done = 0;
                g_notIota = 0;
            }
        }
    }
}

// ---------------------------------------------------------------------------
extern "C" void kernel_launch(void* const* d_in, const int* in_sizes, int n_in,
                              void* d_out, int out_size) {
    const float* masked_dofs = (const float*)d_in[0];
    const float* full_dofs   = (const float*)d_in[1];
    const float* k_tor       = (const float*)d_in[2];
    const float* n_per       = (const float*)d_in[3];
    const float* delta       = (const float*)d_in[4];
    const int*   mask_idx    = (const int*)d_in[5];
    const int*   parent      = (const int*)d_in[6];
    const int*   tors        = (const int*)d_in[7];

    int K = in_sizes[0] / 9;
    int N = in_sizes[1] / 9;
    int M = in_sizes[2];

    int b1 = (N < L1B) ? N : L1B;
    int b2 = (N < L2B) ? N : L2B;
    int b3 = (N < L3B) ? N : L3B;

    const int TB = 256;
    k_check<<<256, TB>>>(mask_idx, K);
    k_local<<<(N + TB - 1) / TB, TB>>>(full_dofs, masked_dofs, N, K);
    k_scatter<<<256, TB>>>(masked_dofs, mask_idx, K);
    k_glob<<<(b1 + TB - 1) / TB, TB>>>(parent, 0, b1, 1);
    if (b2 > b1)
        k_glob<<<(b2 - b1 + TB - 1) / TB, TB>>>(parent, b1, b2, b1);
    if (b3 > b2)
        k_glob<<<(b3 - b2 + TB - 1) / TB, TB>>>(parent, b2, b3, b2);
    if (N > b3)
        k_coords<<<(N - b3 + TB - 1) / TB, TB>>>(parent, N);
    k_energy<<<(M + TB - 1) / TB, TB>>>(tors, k_tor, n_per, delta, M,
                                        (float*)d_out);
}